// round 16
// baseline (speedup 1.0000x reference)
#include <cuda_runtime.h>
#include <math.h>
#include <float.h>

#define NN 50000
#define NE 800000
#define MP 3
#define DF 256
#define NH 8
#define DOUTD 32
#define HIDN 128
#define RTOT (MP * NN)
#define ELLW 64

// ---------------- scratch (static device memory; no allocation) ----------------
__device__ float g_feat[(size_t)MP * NN * DF];
__device__ float g_z[(size_t)MP * NN * DF];
__device__ float g_el[MP * NN * NH];
__device__ float g_er[MP * NN * NH];
__device__ int   g_cnt[MP * NN];          // zeroed by k_final tail (bss-zero on first call)
__device__ int   g_ell[(size_t)MP * NN * ELLW];   // edges by dst, ELL format
__device__ float g_w[MP];
__device__ float g_beta[MP];

// ---------------- tf32 mma helpers ----------------
__device__ __forceinline__ unsigned f2tf(float x) {
    unsigned u; asm("cvt.rna.tf32.f32 %0, %1;" : "=r"(u) : "f"(x)); return u;
}
__device__ __forceinline__ void mma8(float* c, const unsigned* a, unsigned b0, unsigned b1) {
    asm volatile("mma.sync.aligned.m16n8k8.row.col.f32.tf32.tf32.f32 "
                 "{%0,%1,%2,%3}, {%4,%5,%6,%7}, {%8,%9}, {%0,%1,%2,%3};"
                 : "+f"(c[0]), "+f"(c[1]), "+f"(c[2]), "+f"(c[3])
                 : "r"(a[0]), "r"(a[1]), "r"(a[2]), "r"(a[3]), "r"(b0), "r"(b1));
}

// ---------------- ELL build: one pass, atomic cursor per dst ----------------
__global__ void k_scatter_ell(const int* __restrict__ src, const int* __restrict__ dst) {
    int i = blockIdx.x * blockDim.x + threadIdx.x;
    if (i >= MP * NE) return;
    int m = i / NE;
    int t = dst[i];
    int pos = atomicAdd(&g_cnt[m * NN + t], 1);
    if (pos < ELLW) g_ell[((size_t)m * NN + t) * ELLW + pos] = src[i];
}

// ---------------- GEMM1 (tensor): feat[m] = h @ W_gat[m] + fused el/er epilogue ----------------
__global__ __launch_bounds__(256, 2) void k_gemm_feat(const float* __restrict__ A,
                                                      const float* __restrict__ Wg,
                                                      const float* __restrict__ attl,
                                                      const float* __restrict__ attr) {
    __shared__ unsigned As[2][128][20];
    __shared__ unsigned Bs[2][16][136];
    const int m = blockIdx.z;
    const float* B = Wg + (size_t)m * 128 * DF;
    float* C = g_feat + (size_t)m * NN * DF;
    const int rowBase = blockIdx.x * 128;
    const int colBase = blockIdx.y * 128;
    const int tid = threadIdx.x;
    const int wid = tid >> 5, lane = tid & 31;
    const int warpM = wid & 3, warpN = wid >> 2;
    const int t4 = lane >> 2, c4 = lane & 3;

    const int ar = tid >> 2, ac = (tid & 3) * 4;
    const int bk = tid >> 4, bc = (tid & 15) * 4;

    float acc[2][8][4];
#pragma unroll
    for (int i = 0; i < 2; i++)
#pragma unroll
        for (int j = 0; j < 8; j++)
#pragma unroll
            for (int q = 0; q < 4; q++) acc[i][j][q] = 0.f;

#pragma unroll
    for (int p = 0; p < 2; p++) {
        int r = ar + p * 64;
        int gr = rowBase + r; if (gr >= NN) gr = NN - 1;
        float4 v = *(const float4*)&A[(size_t)gr * 128 + ac];
        unsigned uv[4] = {f2tf(v.x), f2tf(v.y), f2tf(v.z), f2tf(v.w)};
        *(uint4*)&As[0][r][ac] = *(uint4*)uv;
        int c = bc + p * 64;
        float4 bv = *(const float4*)&B[(size_t)bk * DF + colBase + c];
        unsigned bu[4] = {f2tf(bv.x), f2tf(bv.y), f2tf(bv.z), f2tf(bv.w)};
        *(uint4*)&Bs[0][bk][c] = *(uint4*)bu;
    }
    __syncthreads();

    int cur = 0;
#pragma unroll
    for (int kt = 0; kt < 128; kt += 16) {
        float4 rA[2], rB[2];
        const bool more = (kt + 16 < 128);
        if (more) {
#pragma unroll
            for (int p = 0; p < 2; p++) {
                int r = ar + p * 64;
                int gr = rowBase + r; if (gr >= NN) gr = NN - 1;
                rA[p] = *(const float4*)&A[(size_t)gr * 128 + kt + 16 + ac];
                rB[p] = *(const float4*)&B[(size_t)(kt + 16 + bk) * DF + colBase + bc + p * 64];
            }
        }
#pragma unroll
        for (int ks = 0; ks < 2; ks++) {
            const int k = ks * 8;
            unsigned af[2][4];
#pragma unroll
            for (int mt = 0; mt < 2; mt++) {
                int r = warpM * 32 + mt * 16 + t4;
                af[mt][0] = As[cur][r][k + c4];
                af[mt][1] = As[cur][r + 8][k + c4];
                af[mt][2] = As[cur][r][k + c4 + 4];
                af[mt][3] = As[cur][r + 8][k + c4 + 4];
            }
#pragma unroll
            for (int nt = 0; nt < 8; nt++) {
                int n = warpN * 64 + nt * 8 + t4;
                unsigned b0 = Bs[cur][k + c4][n];
                unsigned b1 = Bs[cur][k + c4 + 4][n];
                mma8(acc[0][nt], af[0], b0, b1);
                mma8(acc[1][nt], af[1], b0, b1);
            }
        }
        if (more) {
            int nxt = cur ^ 1;
#pragma unroll
            for (int p = 0; p < 2; p++) {
                int r = ar + p * 64;
                unsigned uv[4] = {f2tf(rA[p].x), f2tf(rA[p].y), f2tf(rA[p].z), f2tf(rA[p].w)};
                *(uint4*)&As[nxt][r][ac] = *(uint4*)uv;
                unsigned bu[4] = {f2tf(rB[p].x), f2tf(rB[p].y), f2tf(rB[p].z), f2tf(rB[p].w)};
                *(uint4*)&Bs[nxt][bk][bc + p * 64] = *(uint4*)bu;
            }
            __syncthreads();
            cur = nxt;
        }
    }

#pragma unroll
    for (int mt = 0; mt < 2; mt++) {
        int r0 = rowBase + warpM * 32 + mt * 16 + t4;
        int r1 = r0 + 8;
#pragma unroll
        for (int nt = 0; nt < 8; nt++) {
            int cg = colBase + warpN * 64 + nt * 8 + c4 * 2;
            if (r0 < NN) { float2 v = {acc[mt][nt][0], acc[mt][nt][1]}; *(float2*)&C[(size_t)r0 * DF + cg] = v; }
            if (r1 < NN) { float2 v = {acc[mt][nt][2], acc[mt][nt][3]}; *(float2*)&C[(size_t)r1 * DF + cg] = v; }
        }
    }

    // fused el/er
    const float* alm = attl + (size_t)m * NH * DOUTD;
    const float* arm = attr + (size_t)m * NH * DOUTD;
#pragma unroll
    for (int half = 0; half < 2; half++) {
        const int head = (colBase + warpN * 64) / 32 + half;
        const float* av = alm + head * DOUTD;
        const float* rv = arm + head * DOUTD;
#pragma unroll
        for (int mt = 0; mt < 2; mt++) {
            float el0 = 0.f, el1 = 0.f, er0 = 0.f, er1 = 0.f;
#pragma unroll
            for (int ntl = 0; ntl < 4; ntl++) {
                int nt = half * 4 + ntl;
                int d = ntl * 8 + c4 * 2;
                float a0 = av[d], a1 = av[d + 1];
                float q0 = rv[d], q1 = rv[d + 1];
                el0 += acc[mt][nt][0] * a0 + acc[mt][nt][1] * a1;
                el1 += acc[mt][nt][2] * a0 + acc[mt][nt][3] * a1;
                er0 += acc[mt][nt][0] * q0 + acc[mt][nt][1] * q1;
                er1 += acc[mt][nt][2] * q0 + acc[mt][nt][3] * q1;
            }
            el0 += __shfl_xor_sync(0xffffffffu, el0, 1); el0 += __shfl_xor_sync(0xffffffffu, el0, 2);
            el1 += __shfl_xor_sync(0xffffffffu, el1, 1); el1 += __shfl_xor_sync(0xffffffffu, el1, 2);
            er0 += __shfl_xor_sync(0xffffffffu, er0, 1); er0 += __shfl_xor_sync(0xffffffffu, er0, 2);
            er1 += __shfl_xor_sync(0xffffffffu, er1, 1); er1 += __shfl_xor_sync(0xffffffffu, er1, 2);
            if (c4 == 0) {
                int r0 = rowBase + warpM * 32 + mt * 16 + t4;
                int r1 = r0 + 8;
                if (r0 < NN) {
                    g_el[((size_t)m * NN + r0) * NH + head] = el0;
                    g_er[((size_t)m * NN + r0) * NH + head] = er0;
                }
                if (r1 < NN) {
                    g_el[((size_t)m * NN + r1) * NH + head] = el1;
                    g_er[((size_t)m * NN + r1) * NH + head] = er1;
                }
            }
        }
    }
}

// ---------------- segment softmax + aggregation (EXACT R11/R14 code — FROZEN, grid (NN,MP)) ----------------
__global__ __launch_bounds__(256) void k_agg(const float* __restrict__ bias) {
    const int t = blockIdx.x, m = blockIdx.y;
    const int tid = threadIdx.x;
    const int k = tid >> 5, lane = tid & 31;
    const int deg = min(g_cnt[m * NN + t], ELLW);
    const float* el = g_el + (size_t)m * NN * NH;
    const int* ss = g_ell + ((size_t)m * NN + t) * ELLW;
    const float erk = g_er[((size_t)m * NN + t) * NH + k];
    const float4* fb4 = (const float4*)(g_feat + (size_t)m * NN * DF + k * DOUTD);
    const int eg = lane >> 3;
    const int d8 = lane & 7;

    float4 acc = make_float4(0.f, 0.f, 0.f, 0.f);

    if (deg > 0) {
        if (deg <= 32) {
            int sj = 0; float e = -FLT_MAX;
            if (lane < deg) {
                sj = ss[lane];
                float ev = el[sj * NH + k] + erk;
                e = ev > 0.f ? ev : 0.2f * ev;
            }
            float mx = e;
#pragma unroll
            for (int o = 16; o > 0; o >>= 1) mx = fmaxf(mx, __shfl_xor_sync(0xffffffffu, mx, o));
            float ex = (lane < deg) ? expf(e - mx) : 0.f;
            float dn = ex;
#pragma unroll
            for (int o = 16; o > 0; o >>= 1) dn += __shfl_xor_sync(0xffffffffu, dn, o);
            float a = ex * (1.f / (dn + 1e-9f));
            for (int q = 0; q < deg; q += 4) {
                int idx = q + eg;
                float aq = __shfl_sync(0xffffffffu, a, idx);
                int sq   = __shfl_sync(0xffffffffu, sj, idx);
                float4 f = fb4[(size_t)sq * (DF / 4) + d8];
                acc.x += aq * f.x; acc.y += aq * f.y; acc.z += aq * f.z; acc.w += aq * f.w;
            }
        } else {
            float mx = -FLT_MAX;
            for (int j = lane; j < deg; j += 32) {
                int s = ss[j];
                float ev = el[s * NH + k] + erk;
                ev = ev > 0.f ? ev : 0.2f * ev;
                mx = fmaxf(mx, ev);
            }
#pragma unroll
            for (int o = 16; o > 0; o >>= 1) mx = fmaxf(mx, __shfl_xor_sync(0xffffffffu, mx, o));
            float dn = 0.f;
            for (int j = lane; j < deg; j += 32) {
                int s = ss[j];
                float ev = el[s * NH + k] + erk;
                ev = ev > 0.f ? ev : 0.2f * ev;
                dn += expf(ev - mx);
            }
#pragma unroll
            for (int o = 16; o > 0; o >>= 1) dn += __shfl_xor_sync(0xffffffffu, dn, o);
            float inv = 1.f / (dn + 1e-9f);
            for (int base = 0; base < deg; base += 32) {
                int jj = base + lane;
                int sj = 0; float a = 0.f;
                if (jj < deg) {
                    sj = ss[jj];
                    float ev = el[sj * NH + k] + erk;
                    ev = ev > 0.f ? ev : 0.2f * ev;
                    a = expf(ev - mx) * inv;
                }
                int cnt = min(32, deg - base);
                for (int q = 0; q < cnt; q += 4) {
                    int idx = q + eg;
                    float aq = __shfl_sync(0xffffffffu, a, idx);
                    int sq   = __shfl_sync(0xffffffffu, sj, idx);
                    float4 f = fb4[(size_t)sq * (DF / 4) + d8];
                    acc.x += aq * f.x; acc.y += aq * f.y; acc.z += aq * f.z; acc.w += aq * f.w;
                }
            }
        }
    }

#pragma unroll
    for (int o = 8; o <= 16; o <<= 1) {
        acc.x += __shfl_xor_sync(0xffffffffu, acc.x, o);
        acc.y += __shfl_xor_sync(0xffffffffu, acc.y, o);
        acc.z += __shfl_xor_sync(0xffffffffu, acc.z, o);
        acc.w += __shfl_xor_sync(0xffffffffu, acc.w, o);
    }

    if (lane < 8) {
        int d0 = k * DOUTD + lane * 4;
        float4 b = *(const float4*)&bias[m * DF + d0];
        float4 v;
        v.x = acc.x + b.x; v.y = acc.y + b.y; v.z = acc.z + b.z; v.w = acc.w + b.w;
        v.x = v.x > 0.f ? v.x : expm1f(v.x);
        v.y = v.y > 0.f ? v.y : expm1f(v.y);
        v.z = v.z > 0.f ? v.z : expm1f(v.z);
        v.w = v.w > 0.f ? v.w : expm1f(v.w);
        *(float4*)&g_z[((size_t)m * NN + t) * DF + d0] = v;
    }
}

// ---------------- GEMM2 (tensor): fused semantic attention logits ----------------
__global__ __launch_bounds__(256, 2) void k_gemm_sem(const float* __restrict__ W1,
                                                     const float* __restrict__ b1,
                                                     const float* __restrict__ w2) {
    __shared__ unsigned As[2][128][20];
    __shared__ unsigned Bs[2][16][136];
    __shared__ float s_w[MP];
    const float* A = g_z;
    const int rowBase = blockIdx.x * 128;
    const int tid = threadIdx.x;
    const int wid = tid >> 5, lane = tid & 31;
    const int warpM = wid & 3, warpN = wid >> 2;
    const int t4 = lane >> 2, c4 = lane & 3;

    const int ar = tid >> 2, ac = (tid & 3) * 4;
    const int bk = tid >> 4, bc = (tid & 15) * 4;

    float acc[2][8][4];
#pragma unroll
    for (int i = 0; i < 2; i++)
#pragma unroll
        for (int j = 0; j < 8; j++)
#pragma unroll
            for (int q = 0; q < 4; q++) acc[i][j][q] = 0.f;

    if (tid < MP) s_w[tid] = 0.f;

#pragma unroll
    for (int p = 0; p < 2; p++) {
        int r = ar + p * 64;
        int gr = rowBase + r; if (gr >= RTOT) gr = RTOT - 1;
        float4 v = *(const float4*)&A[(size_t)gr * DF + ac];
        unsigned uv[4] = {f2tf(v.x), f2tf(v.y), f2tf(v.z), f2tf(v.w)};
        *(uint4*)&As[0][r][ac] = *(uint4*)uv;
        int c = bc + p * 64;
        float4 bv = *(const float4*)&W1[(size_t)bk * HIDN + c];
        unsigned bu[4] = {f2tf(bv.x), f2tf(bv.y), f2tf(bv.z), f2tf(bv.w)};
        *(uint4*)&Bs[0][bk][c] = *(uint4*)bu;
    }
    __syncthreads();

    int cur = 0;
#pragma unroll
    for (int kt = 0; kt < 256; kt += 16) {
        float4 rA[2], rB[2];
        const bool more = (kt + 16 < 256);
        if (more) {
#pragma unroll
            for (int p = 0; p < 2; p++) {
                int r = ar + p * 64;
                int gr = rowBase + r; if (gr >= RTOT) gr = RTOT - 1;
                rA[p] = *(const float4*)&A[(size_t)gr * DF + kt + 16 + ac];
                rB[p] = *(const float4*)&W1[(size_t)(kt + 16 + bk) * HIDN + bc + p * 64];
            }
        }
#pragma unroll
        for (int ks = 0; ks < 2; ks++) {
            const int k = ks * 8;
            unsigned af[2][4];
#pragma unroll
            for (int mt = 0; mt < 2; mt++) {
                int r = warpM * 32 + mt * 16 + t4;
                af[mt][0] = As[cur][r][k + c4];
                af[mt][1] = As[cur][r + 8][k + c4];
                af[mt][2] = As[cur][r][k + c4 + 4];
                af[mt][3] = As[cur][r + 8][k + c4 + 4];
            }
#pragma unroll
            for (int nt = 0; nt < 8; nt++) {
                int n = warpN * 64 + nt * 8 + t4;
                unsigned b0 = Bs[cur][k + c4][n];
                unsigned b1v = Bs[cur][k + c4 + 4][n];
                mma8(acc[0][nt], af[0], b0, b1v);
                mma8(acc[1][nt], af[1], b0, b1v);
            }
        }
        if (more) {
            int nxt = cur ^ 1;
#pragma unroll
            for (int p = 0; p < 2; p++) {
                int r = ar + p * 64;
                unsigned uv[4] = {f2tf(rA[p].x), f2tf(rA[p].y), f2tf(rA[p].z), f2tf(rA[p].w)};
                *(uint4*)&As[nxt][r][ac] = *(uint4*)uv;
                unsigned bu[4] = {f2tf(rB[p].x), f2tf(rB[p].y), f2tf(rB[p].z), f2tf(rB[p].w)};
                *(uint4*)&Bs[nxt][bk][bc + p * 64] = *(uint4*)bu;
            }
            __syncthreads();
            cur = nxt;
        }
    }

#pragma unroll
    for (int mt = 0; mt < 2; mt++) {
        float p0 = 0.f, p1 = 0.f;
#pragma unroll
        for (int nt = 0; nt < 8; nt++) {
            int cg = warpN * 64 + nt * 8 + c4 * 2;
            float b1a = b1[cg], b1b = b1[cg + 1];
            float w2a = w2[cg], w2b = w2[cg + 1];
            p0 += tanhf(acc[mt][nt][0] + b1a) * w2a + tanhf(acc[mt][nt][1] + b1b) * w2b;
            p1 += tanhf(acc[mt][nt][2] + b1a) * w2a + tanhf(acc[mt][nt][3] + b1b) * w2b;
        }
        p0 += __shfl_xor_sync(0xffffffffu, p0, 1);
        p0 += __shfl_xor_sync(0xffffffffu, p0, 2);
        p1 += __shfl_xor_sync(0xffffffffu, p1, 1);
        p1 += __shfl_xor_sync(0xffffffffu, p1, 2);
        if (c4 == 0) {
            int r0 = rowBase + warpM * 32 + mt * 16 + t4;
            int r1 = r0 + 8;
            if (r0 < RTOT) atomicAdd(&s_w[r0 / NN], p0);
            if (r1 < RTOT) atomicAdd(&s_w[r1 / NN], p1);
        }
    }
    __syncthreads();
    if (tid < MP) atomicAdd(&g_w[tid], s_w[tid]);
}

__global__ void k_beta() {
    if (threadIdx.x == 0 && blockIdx.x == 0) {
        float w0 = g_w[0] / (float)NN, w1 = g_w[1] / (float)NN, w2v = g_w[2] / (float)NN;
        float mx = fmaxf(w0, fmaxf(w1, w2v));
        float e0 = expf(w0 - mx), e1 = expf(w1 - mx), e2 = expf(w2v - mx);
        float s = e0 + e1 + e2;
        g_beta[0] = e0 / s; g_beta[1] = e1 / s; g_beta[2] = e2 / s;
    }
}

// final combine (float4) + zero g_cnt/g_w for the next graph replay
__global__ void k_final(float* __restrict__ out) {
    int i = blockIdx.x * blockDim.x + threadIdx.x;
    if (i < MP * NN) g_cnt[i] = 0;
    if (i < MP) g_w[i] = 0.f;
    if (i >= NN * DF / 4) return;
    float b0 = g_beta[0], b1 = g_beta[1], b2 = g_beta[2];
    const float4* z0 = (const float4*)g_z;
    const float4* z1 = (const float4*)(g_z + (size_t)NN * DF);
    const float4* z2 = (const float4*)(g_z + (size_t)2 * NN * DF);
    float4 a = z0[i], b = z1[i], c = z2[i];
    float4 v;
    v.x = b0 * a.x + b1 * b.x + b2 * c.x;
    v.y = b0 * a.y + b1 * b.y + b2 * c.y;
    v.z = b0 * a.z + b1 * b.z + b2 * c.z;
    v.w = b0 * a.w + b1 * b.w + b2 * c.w;
    ((float4*)out)[i] = v;
}

extern "C" void kernel_launch(void* const* d_in, const int* in_sizes, int n_in,
                              void* d_out, int out_size) {
    const float* h  = (const float*)d_in[0];
    const float* Wg = (const float*)d_in[1];
    const float* al = (const float*)d_in[2];
    const float* ar = (const float*)d_in[3];
    const float* bg = (const float*)d_in[4];
    const float* W1 = (const float*)d_in[5];
    const float* b1 = (const float*)d_in[6];
    const float* w2 = (const float*)d_in[7];
    const int* src  = (const int*)d_in[8];
    const int* dst  = (const int*)d_in[9];
    float* out = (float*)d_out;

    // g_cnt/g_w zeroed by previous k_final (bss-zero on very first call).
    k_scatter_ell<<<(MP * NE + 255) / 256, 256>>>(src, dst);
    k_gemm_feat<<<dim3((NN + 127) / 128, DF / 128, MP), 256>>>(h, Wg, al, ar);
    k_agg<<<dim3(NN, MP), 256>>>(bg);
    k_gemm_sem<<<(RTOT + 127) / 128, 256>>>(W1, b1, w2);
    k_beta<<<1, 1>>>();
    k_final<<<(NN * DF / 4 + 255) / 256, 256>>>(out);
}

// round 17
// speedup vs baseline: 1.4549x; 1.4549x over previous
#include <cuda_runtime.h>
#include <math.h>
#include <float.h>

#define NN 50000
#define NE 800000
#define MP 3
#define DF 256
#define NH 8
#define DOUTD 32
#define HIDN 128
#define RTOT (MP * NN)
#define ELLW 64

// ---------------- scratch (static device memory; no allocation) ----------------
__device__ float g_feat[(size_t)MP * NN * DF];
__device__ float g_z[(size_t)MP * NN * DF];
__device__ float g_el[MP * NN * NH];
__device__ float g_er[MP * NN * NH];
__device__ int   g_cnt[MP * NN];          // zeroed by k_final tail (bss-zero on first call)
__device__ int   g_ell[(size_t)MP * NN * ELLW];   // edges by dst, ELL format
__device__ float g_w[MP];
__device__ float g_beta[MP];

// ---------------- tf32 mma helpers ----------------
__device__ __forceinline__ unsigned f2tf(float x) {
    unsigned u; asm("cvt.rna.tf32.f32 %0, %1;" : "=r"(u) : "f"(x)); return u;
}
__device__ __forceinline__ void mma8(float* c, const unsigned* a, unsigned b0, unsigned b1) {
    asm volatile("mma.sync.aligned.m16n8k8.row.col.f32.tf32.tf32.f32 "
                 "{%0,%1,%2,%3}, {%4,%5,%6,%7}, {%8,%9}, {%0,%1,%2,%3};"
                 : "+f"(c[0]), "+f"(c[1]), "+f"(c[2]), "+f"(c[3])
                 : "r"(a[0]), "r"(a[1]), "r"(a[2]), "r"(a[3]), "r"(b0), "r"(b1));
}

// ---------------- ELL build: one pass, atomic cursor per dst ----------------
__global__ void k_scatter_ell(const int* __restrict__ src, const int* __restrict__ dst) {
    int i = blockIdx.x * blockDim.x + threadIdx.x;
    if (i >= MP * NE) return;
    int m = i / NE;
    int t = dst[i];
    int pos = atomicAdd(&g_cnt[m * NN + t], 1);
    if (pos < ELLW) g_ell[((size_t)m * NN + t) * ELLW + pos] = src[i];
}

// ---------------- GEMM1 (tensor): feat[m] = h @ W_gat[m] + fused el/er epilogue ----------------
__global__ __launch_bounds__(256, 2) void k_gemm_feat(const float* __restrict__ A,
                                                      const float* __restrict__ Wg,
                                                      const float* __restrict__ attl,
                                                      const float* __restrict__ attr) {
    __shared__ unsigned As[2][128][20];
    __shared__ unsigned Bs[2][16][136];
    const int m = blockIdx.z;
    const float* B = Wg + (size_t)m * 128 * DF;
    float* C = g_feat + (size_t)m * NN * DF;
    const int rowBase = blockIdx.x * 128;
    const int colBase = blockIdx.y * 128;
    const int tid = threadIdx.x;
    const int wid = tid >> 5, lane = tid & 31;
    const int warpM = wid & 3, warpN = wid >> 2;
    const int t4 = lane >> 2, c4 = lane & 3;

    const int ar = tid >> 2, ac = (tid & 3) * 4;
    const int bk = tid >> 4, bc = (tid & 15) * 4;

    float acc[2][8][4];
#pragma unroll
    for (int i = 0; i < 2; i++)
#pragma unroll
        for (int j = 0; j < 8; j++)
#pragma unroll
            for (int q = 0; q < 4; q++) acc[i][j][q] = 0.f;

#pragma unroll
    for (int p = 0; p < 2; p++) {
        int r = ar + p * 64;
        int gr = rowBase + r; if (gr >= NN) gr = NN - 1;
        float4 v = *(const float4*)&A[(size_t)gr * 128 + ac];
        unsigned uv[4] = {f2tf(v.x), f2tf(v.y), f2tf(v.z), f2tf(v.w)};
        *(uint4*)&As[0][r][ac] = *(uint4*)uv;
        int c = bc + p * 64;
        float4 bv = *(const float4*)&B[(size_t)bk * DF + colBase + c];
        unsigned bu[4] = {f2tf(bv.x), f2tf(bv.y), f2tf(bv.z), f2tf(bv.w)};
        *(uint4*)&Bs[0][bk][c] = *(uint4*)bu;
    }
    __syncthreads();

    int cur = 0;
    for (int kt = 0; kt < 128; kt += 16) {
        float4 rA[2], rB[2];
        const bool more = (kt + 16 < 128);
        if (more) {
#pragma unroll
            for (int p = 0; p < 2; p++) {
                int r = ar + p * 64;
                int gr = rowBase + r; if (gr >= NN) gr = NN - 1;
                rA[p] = *(const float4*)&A[(size_t)gr * 128 + kt + 16 + ac];
                rB[p] = *(const float4*)&B[(size_t)(kt + 16 + bk) * DF + colBase + bc + p * 64];
            }
        }
#pragma unroll
        for (int ks = 0; ks < 2; ks++) {
            const int k = ks * 8;
            unsigned af[2][4];
#pragma unroll
            for (int mt = 0; mt < 2; mt++) {
                int r = warpM * 32 + mt * 16 + t4;
                af[mt][0] = As[cur][r][k + c4];
                af[mt][1] = As[cur][r + 8][k + c4];
                af[mt][2] = As[cur][r][k + c4 + 4];
                af[mt][3] = As[cur][r + 8][k + c4 + 4];
            }
#pragma unroll
            for (int nt = 0; nt < 8; nt++) {
                int n = warpN * 64 + nt * 8 + t4;
                unsigned b0 = Bs[cur][k + c4][n];
                unsigned b1 = Bs[cur][k + c4 + 4][n];
                mma8(acc[0][nt], af[0], b0, b1);
                mma8(acc[1][nt], af[1], b0, b1);
            }
        }
        if (more) {
            int nxt = cur ^ 1;
#pragma unroll
            for (int p = 0; p < 2; p++) {
                int r = ar + p * 64;
                unsigned uv[4] = {f2tf(rA[p].x), f2tf(rA[p].y), f2tf(rA[p].z), f2tf(rA[p].w)};
                *(uint4*)&As[nxt][r][ac] = *(uint4*)uv;
                unsigned bu[4] = {f2tf(rB[p].x), f2tf(rB[p].y), f2tf(rB[p].z), f2tf(rB[p].w)};
                *(uint4*)&Bs[nxt][bk][bc + p * 64] = *(uint4*)bu;
            }
            __syncthreads();
            cur = nxt;
        }
    }

#pragma unroll
    for (int mt = 0; mt < 2; mt++) {
        int r0 = rowBase + warpM * 32 + mt * 16 + t4;
        int r1 = r0 + 8;
#pragma unroll
        for (int nt = 0; nt < 8; nt++) {
            int cg = colBase + warpN * 64 + nt * 8 + c4 * 2;
            if (r0 < NN) { float2 v = {acc[mt][nt][0], acc[mt][nt][1]}; *(float2*)&C[(size_t)r0 * DF + cg] = v; }
            if (r1 < NN) { float2 v = {acc[mt][nt][2], acc[mt][nt][3]}; *(float2*)&C[(size_t)r1 * DF + cg] = v; }
        }
    }

    // fused el/er
    const float* alm = attl + (size_t)m * NH * DOUTD;
    const float* arm = attr + (size_t)m * NH * DOUTD;
#pragma unroll
    for (int half = 0; half < 2; half++) {
        const int head = (colBase + warpN * 64) / 32 + half;
        const float* av = alm + head * DOUTD;
        const float* rv = arm + head * DOUTD;
#pragma unroll
        for (int mt = 0; mt < 2; mt++) {
            float el0 = 0.f, el1 = 0.f, er0 = 0.f, er1 = 0.f;
#pragma unroll
            for (int ntl = 0; ntl < 4; ntl++) {
                int nt = half * 4 + ntl;
                int d = ntl * 8 + c4 * 2;
                float a0 = av[d], a1 = av[d + 1];
                float q0 = rv[d], q1 = rv[d + 1];
                el0 += acc[mt][nt][0] * a0 + acc[mt][nt][1] * a1;
                el1 += acc[mt][nt][2] * a0 + acc[mt][nt][3] * a1;
                er0 += acc[mt][nt][0] * q0 + acc[mt][nt][1] * q1;
                er1 += acc[mt][nt][2] * q0 + acc[mt][nt][3] * q1;
            }
            el0 += __shfl_xor_sync(0xffffffffu, el0, 1); el0 += __shfl_xor_sync(0xffffffffu, el0, 2);
            el1 += __shfl_xor_sync(0xffffffffu, el1, 1); el1 += __shfl_xor_sync(0xffffffffu, el1, 2);
            er0 += __shfl_xor_sync(0xffffffffu, er0, 1); er0 += __shfl_xor_sync(0xffffffffu, er0, 2);
            er1 += __shfl_xor_sync(0xffffffffu, er1, 1); er1 += __shfl_xor_sync(0xffffffffu, er1, 2);
            if (c4 == 0) {
                int r0 = rowBase + warpM * 32 + mt * 16 + t4;
                int r1 = r0 + 8;
                if (r0 < NN) {
                    g_el[((size_t)m * NN + r0) * NH + head] = el0;
                    g_er[((size_t)m * NN + r0) * NH + head] = er0;
                }
                if (r1 < NN) {
                    g_el[((size_t)m * NN + r1) * NH + head] = el1;
                    g_er[((size_t)m * NN + r1) * NH + head] = er1;
                }
            }
        }
    }
}

// ---------------- segment softmax + aggregation (EXACT R11 code — FROZEN, grid (NN,MP)) ----------------
__global__ __launch_bounds__(256) void k_agg(const float* __restrict__ bias) {
    const int t = blockIdx.x, m = blockIdx.y;
    const int tid = threadIdx.x;
    const int k = tid >> 5, lane = tid & 31;
    const int deg = min(g_cnt[m * NN + t], ELLW);
    const float* el = g_el + (size_t)m * NN * NH;
    const int* ss = g_ell + ((size_t)m * NN + t) * ELLW;
    const float erk = g_er[((size_t)m * NN + t) * NH + k];
    const float4* fb4 = (const float4*)(g_feat + (size_t)m * NN * DF + k * DOUTD);
    const int eg = lane >> 3;
    const int d8 = lane & 7;

    float4 acc = make_float4(0.f, 0.f, 0.f, 0.f);

    if (deg > 0) {
        if (deg <= 32) {
            int sj = 0; float e = -FLT_MAX;
            if (lane < deg) {
                sj = ss[lane];
                float ev = el[sj * NH + k] + erk;
                e = ev > 0.f ? ev : 0.2f * ev;
            }
            float mx = e;
#pragma unroll
            for (int o = 16; o > 0; o >>= 1) mx = fmaxf(mx, __shfl_xor_sync(0xffffffffu, mx, o));
            float ex = (lane < deg) ? expf(e - mx) : 0.f;
            float dn = ex;
#pragma unroll
            for (int o = 16; o > 0; o >>= 1) dn += __shfl_xor_sync(0xffffffffu, dn, o);
            float a = ex * (1.f / (dn + 1e-9f));
            for (int q = 0; q < deg; q += 4) {
                int idx = q + eg;
                float aq = __shfl_sync(0xffffffffu, a, idx);
                int sq   = __shfl_sync(0xffffffffu, sj, idx);
                float4 f = fb4[(size_t)sq * (DF / 4) + d8];
                acc.x += aq * f.x; acc.y += aq * f.y; acc.z += aq * f.z; acc.w += aq * f.w;
            }
        } else {
            float mx = -FLT_MAX;
            for (int j = lane; j < deg; j += 32) {
                int s = ss[j];
                float ev = el[s * NH + k] + erk;
                ev = ev > 0.f ? ev : 0.2f * ev;
                mx = fmaxf(mx, ev);
            }
#pragma unroll
            for (int o = 16; o > 0; o >>= 1) mx = fmaxf(mx, __shfl_xor_sync(0xffffffffu, mx, o));
            float dn = 0.f;
            for (int j = lane; j < deg; j += 32) {
                int s = ss[j];
                float ev = el[s * NH + k] + erk;
                ev = ev > 0.f ? ev : 0.2f * ev;
                dn += expf(ev - mx);
            }
#pragma unroll
            for (int o = 16; o > 0; o >>= 1) dn += __shfl_xor_sync(0xffffffffu, dn, o);
            float inv = 1.f / (dn + 1e-9f);
            for (int base = 0; base < deg; base += 32) {
                int jj = base + lane;
                int sj = 0; float a = 0.f;
                if (jj < deg) {
                    sj = ss[jj];
                    float ev = el[sj * NH + k] + erk;
                    ev = ev > 0.f ? ev : 0.2f * ev;
                    a = expf(ev - mx) * inv;
                }
                int cnt = min(32, deg - base);
                for (int q = 0; q < cnt; q += 4) {
                    int idx = q + eg;
                    float aq = __shfl_sync(0xffffffffu, a, idx);
                    int sq   = __shfl_sync(0xffffffffu, sj, idx);
                    float4 f = fb4[(size_t)sq * (DF / 4) + d8];
                    acc.x += aq * f.x; acc.y += aq * f.y; acc.z += aq * f.z; acc.w += aq * f.w;
                }
            }
        }
    }

#pragma unroll
    for (int o = 8; o <= 16; o <<= 1) {
        acc.x += __shfl_xor_sync(0xffffffffu, acc.x, o);
        acc.y += __shfl_xor_sync(0xffffffffu, acc.y, o);
        acc.z += __shfl_xor_sync(0xffffffffu, acc.z, o);
        acc.w += __shfl_xor_sync(0xffffffffu, acc.w, o);
    }

    if (lane < 8) {
        int d0 = k * DOUTD + lane * 4;
        float4 b = *(const float4*)&bias[m * DF + d0];
        float4 v;
        v.x = acc.x + b.x; v.y = acc.y + b.y; v.z = acc.z + b.z; v.w = acc.w + b.w;
        v.x = v.x > 0.f ? v.x : expm1f(v.x);
        v.y = v.y > 0.f ? v.y : expm1f(v.y);
        v.z = v.z > 0.f ? v.z : expm1f(v.z);
        v.w = v.w > 0.f ? v.w : expm1f(v.w);
        *(float4*)&g_z[((size_t)m * NN + t) * DF + d0] = v;
    }
}

// ---------------- GEMM2 (tensor): fused semantic attention logits ----------------
__global__ __launch_bounds__(256, 2) void k_gemm_sem(const float* __restrict__ W1,
                                                     const float* __restrict__ b1,
                                                     const float* __restrict__ w2) {
    __shared__ unsigned As[2][128][20];
    __shared__ unsigned Bs[2][16][136];
    __shared__ float s_w[MP];
    const float* A = g_z;
    const int rowBase = blockIdx.x * 128;
    const int tid = threadIdx.x;
    const int wid = tid >> 5, lane = tid & 31;
    const int warpM = wid & 3, warpN = wid >> 2;
    const int t4 = lane >> 2, c4 = lane & 3;

    const int ar = tid >> 2, ac = (tid & 3) * 4;
    const int bk = tid >> 4, bc = (tid & 15) * 4;

    float acc[2][8][4];
#pragma unroll
    for (int i = 0; i < 2; i++)
#pragma unroll
        for (int j = 0; j < 8; j++)
#pragma unroll
            for (int q = 0; q < 4; q++) acc[i][j][q] = 0.f;

    if (tid < MP) s_w[tid] = 0.f;

#pragma unroll
    for (int p = 0; p < 2; p++) {
        int r = ar + p * 64;
        int gr = rowBase + r; if (gr >= RTOT) gr = RTOT - 1;
        float4 v = *(const float4*)&A[(size_t)gr * DF + ac];
        unsigned uv[4] = {f2tf(v.x), f2tf(v.y), f2tf(v.z), f2tf(v.w)};
        *(uint4*)&As[0][r][ac] = *(uint4*)uv;
        int c = bc + p * 64;
        float4 bv = *(const float4*)&W1[(size_t)bk * HIDN + c];
        unsigned bu[4] = {f2tf(bv.x), f2tf(bv.y), f2tf(bv.z), f2tf(bv.w)};
        *(uint4*)&Bs[0][bk][c] = *(uint4*)bu;
    }
    __syncthreads();

    int cur = 0;
    for (int kt = 0; kt < 256; kt += 16) {
        float4 rA[2], rB[2];
        const bool more = (kt + 16 < 256);
        if (more) {
#pragma unroll
            for (int p = 0; p < 2; p++) {
                int r = ar + p * 64;
                int gr = rowBase + r; if (gr >= RTOT) gr = RTOT - 1;
                rA[p] = *(const float4*)&A[(size_t)gr * DF + kt + 16 + ac];
                rB[p] = *(const float4*)&W1[(size_t)(kt + 16 + bk) * HIDN + bc + p * 64];
            }
        }
#pragma unroll
        for (int ks = 0; ks < 2; ks++) {
            const int k = ks * 8;
            unsigned af[2][4];
#pragma unroll
            for (int mt = 0; mt < 2; mt++) {
                int r = warpM * 32 + mt * 16 + t4;
                af[mt][0] = As[cur][r][k + c4];
                af[mt][1] = As[cur][r + 8][k + c4];
                af[mt][2] = As[cur][r][k + c4 + 4];
                af[mt][3] = As[cur][r + 8][k + c4 + 4];
            }
#pragma unroll
            for (int nt = 0; nt < 8; nt++) {
                int n = warpN * 64 + nt * 8 + t4;
                unsigned b0 = Bs[cur][k + c4][n];
                unsigned b1v = Bs[cur][k + c4 + 4][n];
                mma8(acc[0][nt], af[0], b0, b1v);
                mma8(acc[1][nt], af[1], b0, b1v);
            }
        }
        if (more) {
            int nxt = cur ^ 1;
#pragma unroll
            for (int p = 0; p < 2; p++) {
                int r = ar + p * 64;
                unsigned uv[4] = {f2tf(rA[p].x), f2tf(rA[p].y), f2tf(rA[p].z), f2tf(rA[p].w)};
                *(uint4*)&As[nxt][r][ac] = *(uint4*)uv;
                unsigned bu[4] = {f2tf(rB[p].x), f2tf(rB[p].y), f2tf(rB[p].z), f2tf(rB[p].w)};
                *(uint4*)&Bs[nxt][bk][bc + p * 64] = *(uint4*)bu;
            }
            __syncthreads();
            cur = nxt;
        }
    }

#pragma unroll
    for (int mt = 0; mt < 2; mt++) {
        float p0 = 0.f, p1 = 0.f;
#pragma unroll
        for (int nt = 0; nt < 8; nt++) {
            int cg = warpN * 64 + nt * 8 + c4 * 2;
            float b1a = b1[cg], b1b = b1[cg + 1];
            float w2a = w2[cg], w2b = w2[cg + 1];
            p0 += tanhf(acc[mt][nt][0] + b1a) * w2a + tanhf(acc[mt][nt][1] + b1b) * w2b;
            p1 += tanhf(acc[mt][nt][2] + b1a) * w2a + tanhf(acc[mt][nt][3] + b1b) * w2b;
        }
        p0 += __shfl_xor_sync(0xffffffffu, p0, 1);
        p0 += __shfl_xor_sync(0xffffffffu, p0, 2);
        p1 += __shfl_xor_sync(0xffffffffu, p1, 1);
        p1 += __shfl_xor_sync(0xffffffffu, p1, 2);
        if (c4 == 0) {
            int r0 = rowBase + warpM * 32 + mt * 16 + t4;
            int r1 = r0 + 8;
            if (r0 < RTOT) atomicAdd(&s_w[r0 / NN], p0);
            if (r1 < RTOT) atomicAdd(&s_w[r1 / NN], p1);
        }
    }
    __syncthreads();
    if (tid < MP) atomicAdd(&g_w[tid], s_w[tid]);
}

__global__ void k_beta() {
    if (threadIdx.x == 0 && blockIdx.x == 0) {
        float w0 = g_w[0] / (float)NN, w1 = g_w[1] / (float)NN, w2v = g_w[2] / (float)NN;
        float mx = fmaxf(w0, fmaxf(w1, w2v));
        float e0 = expf(w0 - mx), e1 = expf(w1 - mx), e2 = expf(w2v - mx);
        float s = e0 + e1 + e2;
        g_beta[0] = e0 / s; g_beta[1] = e1 / s; g_beta[2] = e2 / s;
    }
}

// final combine (float4) + zero g_cnt/g_w for the next graph replay
__global__ void k_final(float* __restrict__ out) {
    int i = blockIdx.x * blockDim.x + threadIdx.x;
    if (i < MP * NN) g_cnt[i] = 0;
    if (i < MP) g_w[i] = 0.f;
    if (i >= NN * DF / 4) return;
    float b0 = g_beta[0], b1 = g_beta[1], b2 = g_beta[2];
    const float4* z0 = (const float4*)g_z;
    const float4* z1 = (const float4*)(g_z + (size_t)NN * DF);
    const float4* z2 = (const float4*)(g_z + (size_t)2 * NN * DF);
    float4 a = z0[i], b = z1[i], c = z2[i];
    float4 v;
    v.x = b0 * a.x + b1 * b.x + b2 * c.x;
    v.y = b0 * a.y + b1 * b.y + b2 * c.y;
    v.z = b0 * a.z + b1 * b.z + b2 * c.z;
    v.w = b0 * a.w + b1 * b.w + b2 * c.w;
    ((float4*)out)[i] = v;
}

extern "C" void kernel_launch(void* const* d_in, const int* in_sizes, int n_in,
                              void* d_out, int out_size) {
    const float* h  = (const float*)d_in[0];
    const float* Wg = (const float*)d_in[1];
    const float* al = (const float*)d_in[2];
    const float* ar = (const float*)d_in[3];
    const float* bg = (const float*)d_in[4];
    const float* W1 = (const float*)d_in[5];
    const float* b1 = (const float*)d_in[6];
    const float* w2 = (const float*)d_in[7];
    const int* src  = (const int*)d_in[8];
    const int* dst  = (const int*)d_in[9];
    float* out = (float*)d_out;

    // g_cnt/g_w zeroed by previous k_final (bss-zero on very first call).
    k_scatter_ell<<<(MP * NE + 255) / 256, 256>>>(src, dst);
    k_gemm_feat<<<dim3((NN + 127) / 128, DF / 128, MP), 256>>>(h, Wg, al, ar);
    k_agg<<<dim3(NN, MP), 256>>>(bg);
    k_gemm_sem<<<(RTOT + 127) / 128, 256>>>(W1, b1, w2);
    k_beta<<<1, 1>>>();
    k_final<<<(NN * DF / 4 + 255) / 256, 256>>>(out);
}